// round 17
// baseline (speedup 1.0000x reference)
#include <cuda_runtime.h>
#include <cuda_fp16.h>
#include <cstdint>

// Problem dims (fixed by the dataset)
#define O_DIM   4096
#define I_DIM   2048
#define K_ACT   2048
#define N_TOK   4096
#define M_DENSE 8192

// Scratch (device globals; allocation-free rule): fp16 operands
__device__ __half g_Wh[(size_t)O_DIM * K_ACT];   // gathered weight, fp16
__device__ __half g_Bh[(size_t)N_TOK * K_ACT];   // activations, fp16

// ===========================================================================
// Fused prep kernel: two jobs, branch on blockIdx.x.
//   [0, 8192)      : gather weight -> Wh (4 elems/thread, latency-bound)
//   [8192, 12288)  : fp16-convert activations (BW-bound)
// ===========================================================================
#define PREP_G1 8192
#define PREP_G2 4096
#define PREP_GRID (PREP_G1 + PREP_G2)

__global__ __launch_bounds__(256)
void prep_kernel(const float* __restrict__ weight,
                 const int*   __restrict__ idx,
                 const int*   __restrict__ metadata,
                 const float4* __restrict__ input) {
    int blk = blockIdx.x;
    if (blk < PREP_G1) {
        // ---- gather compressed weight -> Wh[o][j], fp16, 4 elems/thread ----
        int t  = blk * 256 + threadIdx.x;
        int o  = t >> 9;
        int j0 = (t & 511) << 2;
        const int4 kd4 = *reinterpret_cast<const int4*>(idx + j0);
        const int* md_row = metadata + (size_t)o * I_DIM;
        const float* w_row = weight + (size_t)o * I_DIM;
        int kd[4] = {kd4.x, kd4.y, kd4.z, kd4.w};
        float v[4];
#pragma unroll
        for (int e = 0; e < 4; e++) {
            int g = kd[e] >> 2;
            int p = kd[e] & 3;
            int2 md = *reinterpret_cast<const int2*>(md_row + 2 * g);
            float r = 0.0f;
            if (md.x == p)      r = __ldg(w_row + 2 * g);
            else if (md.y == p) r = __ldg(w_row + 2 * g + 1);
            v[e] = r;
        }
        __half2 h01 = __floats2half2_rn(v[0], v[1]);
        __half2 h23 = __floats2half2_rn(v[2], v[3]);
        uint2 pack;
        pack.x = *reinterpret_cast<uint32_t*>(&h01);
        pack.y = *reinterpret_cast<uint32_t*>(&h23);
        *reinterpret_cast<uint2*>(g_Wh + (size_t)o * K_ACT + j0) = pack;
    } else {
        // ---- fp16-convert activations: 8 floats/thread ----
        int t = (blk - PREP_G1) * 256 + threadIdx.x;
        float4 f0 = input[t * 2];
        float4 f1 = input[t * 2 + 1];
        __half2 h[4];
        h[0] = __floats2half2_rn(f0.x, f0.y);
        h[1] = __floats2half2_rn(f0.z, f0.w);
        h[2] = __floats2half2_rn(f1.x, f1.y);
        h[3] = __floats2half2_rn(f1.z, f1.w);
        *(reinterpret_cast<uint4*>(g_Bh) + t) = *reinterpret_cast<uint4*>(h);
    }
}

// ===========================================================================
// fp16 mma.sync m16n8k16 GEMM + scatter + smeared zeroing
//   CTA 128x128, KC=64 halves, 256 thr = 8 warps (4m x 2n), warp tile 32x64.
//   3-stage cp.async circular buffer, ONE __syncthreads per K-chunk,
//   per-ks-spread cp.async. Inactive-row zeroing: searched ONCE in the
//   prologue (parallel across threads), then ONE predicated 16B .cs store
//   per thread per kc iteration (32 iters x 16B = the full 512B row stripe).
// ===========================================================================
#define MT      128
#define NT      128
#define KC      64
#define KITERS  (K_ACT / KC)          // 32
#define STAGES  3
#define STRH    72                    // halves per smem row (144 B)
#define ROWB    (STRH * 2)            // 144 bytes
#define A_BYTES (MT * ROWB)           // 18432
#define B_BYTES (NT * ROWB)           // 18432
#define STG_BYTES (A_BYTES + B_BYTES) // 36864
#define SMEM_DYN (STAGES * STG_BYTES) // 110592 B -> 2 CTAs/SM (216 KB)

__device__ __forceinline__ uint32_t smem_u32(const void* p) {
    uint32_t a;
    asm("{ .reg .u64 t; cvta.to.shared.u64 t, %1; cvt.u32.u64 %0, t; }"
        : "=r"(a) : "l"(p));
    return a;
}
__device__ __forceinline__ void ldsm_x4(uint32_t* r, uint32_t addr) {
    asm volatile("ldmatrix.sync.aligned.m8n8.x4.shared.b16 {%0,%1,%2,%3}, [%4];"
                 : "=r"(r[0]), "=r"(r[1]), "=r"(r[2]), "=r"(r[3]) : "r"(addr));
}
__device__ __forceinline__ void mma_f16(float* c, const uint32_t* a,
                                        uint32_t b0, uint32_t b1) {
    asm volatile(
        "mma.sync.aligned.m16n8k16.row.col.f32.f16.f16.f32 "
        "{%0,%1,%2,%3}, {%4,%5,%6,%7}, {%8,%9}, {%0,%1,%2,%3};"
        : "+f"(c[0]), "+f"(c[1]), "+f"(c[2]), "+f"(c[3])
        : "r"(a[0]), "r"(a[1]), "r"(a[2]), "r"(a[3]), "r"(b0), "r"(b1));
}
__device__ __forceinline__ void cp_async16(void* dst_smem, const void* src) {
    uint32_t d;
    asm("{ .reg .u64 t; cvta.to.shared.u64 t, %1; cvt.u32.u64 %0, t; }"
        : "=r"(d) : "l"(dst_smem));
    asm volatile("cp.async.cg.shared.global [%0], [%1], 16;" :: "r"(d), "l"(src));
}
__device__ __forceinline__ void stg_cs_v4(float* p, float x, float y,
                                          float z, float w) {
    asm volatile("st.global.cs.v4.f32 [%0], {%1,%2,%3,%4};"
                 :: "l"(p), "f"(x), "f"(y), "f"(z), "f"(w) : "memory");
}
__device__ __forceinline__ void stg_cs_v2(float* p, float x, float y) {
    asm volatile("st.global.cs.v2.f32 [%0], {%1,%2};"
                 :: "l"(p), "f"(x), "f"(y) : "memory");
}
// binary search: is dense row r active within indices[bm, bm+MT)?
__device__ __forceinline__ bool row_inactive(const int* indices, int bm, int r) {
    int lo = bm, hi = bm + MT;
    while (lo < hi) {
        int mid = (lo + hi) >> 1;
        if (__ldg(indices + mid) < r) lo = mid + 1; else hi = mid;
    }
    return !(lo < bm + MT && __ldg(indices + lo) == r);
}

__global__ __launch_bounds__(256, 2)
void gemm_mma_kernel(const int* __restrict__ indices,
                     float*     __restrict__ out) {
    extern __shared__ char smem[];
    const __half* Ag = g_Wh;
    const __half* Bg = g_Bh;

    const int tid  = threadIdx.x;
    const int lane = tid & 31;
    const int wid  = tid >> 5;
    const int wm   = wid >> 1;        // 0..3 -> m offset wm*32
    const int wn   = wid & 1;         // 0..1 -> n offset wn*64
    const int tm   = blockIdx.y;      // m-tile index 0..31
    const int bm   = tm * MT;
    const int bn   = blockIdx.x * NT;

    // prefetch epilogue scatter rows (latency hidden behind whole mainloop)
    const int r0a = bm + wm * 32 + (lane >> 2);
    const int o_r0  = __ldg(indices + r0a);
    const int o_r8  = __ldg(indices + r0a + 8);
    const int o_r16 = __ldg(indices + r0a + 16);
    const int o_r24 = __ldg(indices + r0a + 24);
    // dense-row interval owned by this m-tile (for inactive-row zeroing)
    const int zlo = (tm == 0) ? 0 : __ldg(indices + bm - 1) + 1;
    const int zhi = (tm == (O_DIM / MT - 1)) ? M_DENSE
                                             : __ldg(indices + bm + MT - 1) + 1;

    float acc[2][8][4];
#pragma unroll
    for (int mi = 0; mi < 2; mi++)
#pragma unroll
        for (int ni = 0; ni < 8; ni++)
#pragma unroll
            for (int q = 0; q < 4; q++) acc[mi][ni][q] = 0.0f;

    // per-thread source/destination for this thread's 8 cp.async ops
    const int ld_row = tid >> 3;                 // 0..31
    const int ld_c   = (tid & 7) << 3;           // halves

    // full-stage loader (prologue only)
    auto load_stage = [&](int kc, int s) {
        char* As = smem + s * STG_BYTES;
        char* Bs = As + A_BYTES;
#pragma unroll
        for (int i = 0; i < 4; i++) {
            int row = ld_row + i * 32;
            cp_async16(As + row * ROWB + ld_c * 2,
                       Ag + (size_t)(bm + row) * K_ACT + kc * KC + ld_c);
            cp_async16(Bs + row * ROWB + ld_c * 2,
                       Bg + (size_t)(bn + row) * K_ACT + kc * KC + ld_c);
        }
    };

    // ldmatrix per-lane row addressing (byte offsets)
    const uint32_t smem_b = smem_u32(smem);
    const int a_row  = wm * 32 + (lane & 7) + (lane & 8);
    const int a_koff = (lane >> 4) << 3;            // halves
    const int b_row  = wn * 64 + (lane & 7) + ((lane >> 4) << 3);
    const int b_koff = (lane & 8);                  // halves

    // prologue: stages 0 and 1 in flight
    load_stage(0, 0);
    asm volatile("cp.async.commit_group;" ::: "memory");
    load_stage(1, 1);
    asm volatile("cp.async.commit_group;" ::: "memory");

    // ---- zeroing setup: each thread claims up to 2 candidate rows; search
    //      runs ONCE here, in parallel across all 256 threads ----
    const int zr0 = zlo + tid;            // covers [zlo, zlo+256)
    const int zr1 = zr0 + 256;            // covers [zlo+256, zlo+512)
    float* zp0 = nullptr;
    float* zp1 = nullptr;
    if (zr0 < zhi && row_inactive(indices, bm, zr0))
        zp0 = out + (size_t)zr0 * N_TOK + bn;
    if (zr1 < zhi && row_inactive(indices, bm, zr1))
        zp1 = out + (size_t)zr1 * N_TOK + bn;

    int s_cur = 0, s_nxt = 2;
    for (int kc = 0; kc < KITERS; kc++) {
        asm volatile("cp.async.wait_group 1;" ::: "memory");   // stage kc ready
        __syncthreads();   // all warps done with compute(kc-1) -> slot s_nxt free

        const bool do_load = (kc + 2 < KITERS);
        char* Asn = smem + s_nxt * STG_BYTES;
        char* Bsn = Asn + A_BYTES;
        const __half* Agn = Ag + (size_t)bm * K_ACT + (kc + 2) * KC;
        const __half* Bgn = Bg + (size_t)bn * K_ACT + (kc + 2) * KC;

        const uint32_t As = smem_b + s_cur * STG_BYTES;
        const uint32_t Bs = As + A_BYTES;
        const uint32_t aAddr = As + a_row * ROWB + a_koff * 2;
        const uint32_t bAddr = Bs + b_row * ROWB + b_koff * 2;

#pragma unroll
        for (int ks = 0; ks < 4; ks++) {
            const int k0b = ks * 32;                // k16 * 2 bytes
            uint32_t aa[2][4];
#pragma unroll
            for (int mi = 0; mi < 2; mi++)
                ldsm_x4(aa[mi], aAddr + mi * 16 * ROWB + k0b);
            uint32_t bb[4][4];
#pragma unroll
            for (int pr = 0; pr < 4; pr++)
                ldsm_x4(bb[pr], bAddr + pr * 16 * ROWB + k0b);
            // 2 of this thread's 8 next-stage cp.async ops while LDSMs fly
            if (do_load) {
                int row = ld_row + ks * 32;
                cp_async16(Asn + row * ROWB + ld_c * 2,
                           Agn + (size_t)row * K_ACT + ld_c);
                cp_async16(Bsn + row * ROWB + ld_c * 2,
                           Bgn + (size_t)row * K_ACT + ld_c);
            }
#pragma unroll
            for (int mi = 0; mi < 2; mi++)
#pragma unroll
                for (int ni = 0; ni < 8; ni++)
                    mma_f16(acc[mi][ni], aa[mi],
                            bb[ni >> 1][(ni & 1) * 2],
                            bb[ni >> 1][(ni & 1) * 2 + 1]);
        }
        // ---- smeared zeroing: one 16B slice of each claimed row per kc ----
        if (zp0) stg_cs_v4(zp0 + kc * 4, 0.f, 0.f, 0.f, 0.f);
        if (zp1) stg_cs_v4(zp1 + kc * 4, 0.f, 0.f, 0.f, 0.f);

        asm volatile("cp.async.commit_group;" ::: "memory");   // stage kc+2 group
        s_cur = (s_cur + 1 == STAGES) ? 0 : s_cur + 1;
        s_nxt = (s_nxt + 1 == STAGES) ? 0 : s_nxt + 1;
    }

    // ---- safety net: intervals larger than 512 rows (normally no-op) ----
    for (int r = zlo + 512 + tid; r < zhi; r += 256) {
        if (!row_inactive(indices, bm, r)) continue;
        float* p = out + (size_t)r * N_TOK + bn;
#pragma unroll
        for (int i = 0; i < NT / 4; i++)
            stg_cs_v4(p + i * 4, 0.f, 0.f, 0.f, 0.f);
    }

    // ---- epilogue: scatter GEMM rows via prefetched indices (.cs stores) ----
    const int orow[2][2] = {{o_r0, o_r8}, {o_r16, o_r24}};
#pragma unroll
    for (int mi = 0; mi < 2; mi++) {
        float* d0 = out + (size_t)orow[mi][0] * N_TOK + bn + wn * 64 + 2 * (lane & 3);
        float* d1 = out + (size_t)orow[mi][1] * N_TOK + bn + wn * 64 + 2 * (lane & 3);
#pragma unroll
        for (int ni = 0; ni < 8; ni++) {
            stg_cs_v2(d0 + ni * 8, acc[mi][ni][0], acc[mi][ni][1]);
            stg_cs_v2(d1 + ni * 8, acc[mi][ni][2], acc[mi][ni][3]);
        }
    }
}

// ===========================================================================
// Host launcher
// ===========================================================================
extern "C" void kernel_launch(void* const* d_in, const int* in_sizes, int n_in,
                              void* d_out, int out_size) {
    const float* input    = (const float*)d_in[0];
    const int*   idx      = (const int*)  d_in[1];
    const float* weight   = (const float*)d_in[2];
    const int*   indices  = (const int*)  d_in[3];
    const int*   metadata = (const int*)  d_in[4];
    if (in_sizes[1] == O_DIM && in_sizes[3] == K_ACT) {
        const int* t = idx; idx = indices; indices = t;
    }
    float* out = (float*)d_out;

    cudaFuncSetAttribute(gemm_mma_kernel,
                         cudaFuncAttributeMaxDynamicSharedMemorySize, SMEM_DYN);

    // 1) fused prep: gather+convert weight, convert activations
    prep_kernel<<<PREP_GRID, 256>>>(weight, idx, metadata, (const float4*)input);
    // 2) tensor-core GEMM + scatter + smeared zeroing
    dim3 grid(N_TOK / NT, O_DIM / MT);   // 32 x 32
    gemm_mma_kernel<<<grid, 256, SMEM_DYN>>>(indices, out);
}